// round 2
// baseline (speedup 1.0000x reference)
#include <cuda_runtime.h>

// Problem constants
constexpr int Bq = 8, Tq = 1024, Dq = 512, Hq = 8, KDq = 64;
constexpr int BT = Bq * Tq;          // 8192
constexpr long long NOUT = (long long)BT * Dq;              // 4,194,304
constexpr long long NATT = (long long)Bq * Hq * Tq * Tq;    // 67,108,864

// Scratch (device globals: allocation-free rule)
__device__ float g_qh[BT * Dq];
__device__ float g_kh[BT * Dq];
__device__ float g_vh[BT * Dq];
__device__ float g_at[BT * Dq];
__device__ float g_q2[Bq * Hq * Tq];
__device__ float g_k2[Bq * Hq * Tq];

__device__ __forceinline__ unsigned f2tf(float x) {
    unsigned r;
    asm("cvt.rna.tf32.f32 %0, %1;" : "=r"(r) : "f"(x));
    return r;
}

__device__ __forceinline__ void mma_m16n8k8(float c[4], const unsigned a[4], const unsigned b[2]) {
    asm volatile(
        "mma.sync.aligned.m16n8k8.row.col.f32.tf32.tf32.f32 "
        "{%0,%1,%2,%3}, {%4,%5,%6,%7}, {%8,%9}, {%0,%1,%2,%3};"
        : "+f"(c[0]), "+f"(c[1]), "+f"(c[2]), "+f"(c[3])
        : "r"(a[0]), "r"(a[1]), "r"(a[2]), "r"(a[3]), "r"(b[0]), "r"(b[1]));
}

// ---------------------------------------------------------------------------
// Generic K=512 GEMM: C[8192,512] = A[8192,512] @ W[512,512]
// Block tile 128x64, 256 threads (warp grid 4x2, warp tile 32x32).
// SPLIT=3: 3xTF32 (fp32-quality); SPLIT=1: plain TF32.
// ---------------------------------------------------------------------------
template <int SPLIT>
__global__ void __launch_bounds__(256) gemm_k512(
    const float* __restrict__ A, const float* __restrict__ W, float* __restrict__ C)
{
    __shared__ float As[128][36];   // pad 36: conflict-free A-frag reads
    __shared__ float Ws[32][72];    // pad 72: conflict-free B-frag reads

    const int tid = threadIdx.x;
    const int lane = tid & 31, warp = tid >> 5;
    const int gid = lane >> 2, tig = lane & 3;
    const int wm = warp & 3, wn = warp >> 2;
    const int m0 = blockIdx.y * 128, n0 = blockIdx.x * 64;

    float acc[2][4][4] = {};

    for (int k0 = 0; k0 < 512; k0 += 32) {
#pragma unroll
        for (int i = 0; i < 4; i++) {
            int idx = tid + i * 256;        // 1024 float4 for A 128x32
            int r = idx >> 3, c = (idx & 7) << 2;
            const float4 v = *reinterpret_cast<const float4*>(A + (size_t)(m0 + r) * 512 + k0 + c);
            As[r][c] = v.x; As[r][c + 1] = v.y; As[r][c + 2] = v.z; As[r][c + 3] = v.w;
        }
#pragma unroll
        for (int i = 0; i < 2; i++) {
            int idx = tid + i * 256;        // 512 float4 for W 32x64
            int r = idx >> 4, c = (idx & 15) << 2;
            const float4 v = *reinterpret_cast<const float4*>(W + (size_t)(k0 + r) * 512 + n0 + c);
            Ws[r][c] = v.x; Ws[r][c + 1] = v.y; Ws[r][c + 2] = v.z; Ws[r][c + 3] = v.w;
        }
        __syncthreads();

#pragma unroll
        for (int s = 0; s < 4; s++) {
            const int kk = s * 8;
            unsigned ah[2][4], al[2][4];
#pragma unroll
            for (int mi = 0; mi < 2; mi++) {
                const int r0 = wm * 32 + mi * 16;
                float x0 = As[r0 + gid][kk + tig];
                float x1 = As[r0 + gid + 8][kk + tig];
                float x2 = As[r0 + gid][kk + tig + 4];
                float x3 = As[r0 + gid + 8][kk + tig + 4];
                ah[mi][0] = f2tf(x0); ah[mi][1] = f2tf(x1);
                ah[mi][2] = f2tf(x2); ah[mi][3] = f2tf(x3);
                if (SPLIT == 3) {
                    al[mi][0] = f2tf(x0 - __uint_as_float(ah[mi][0]));
                    al[mi][1] = f2tf(x1 - __uint_as_float(ah[mi][1]));
                    al[mi][2] = f2tf(x2 - __uint_as_float(ah[mi][2]));
                    al[mi][3] = f2tf(x3 - __uint_as_float(ah[mi][3]));
                }
            }
            unsigned bh[4][2], bl[4][2];
#pragma unroll
            for (int ni = 0; ni < 4; ni++) {
                const int c0 = wn * 32 + ni * 8 + gid;
                float y0 = Ws[kk + tig][c0];
                float y1 = Ws[kk + tig + 4][c0];
                bh[ni][0] = f2tf(y0); bh[ni][1] = f2tf(y1);
                if (SPLIT == 3) {
                    bl[ni][0] = f2tf(y0 - __uint_as_float(bh[ni][0]));
                    bl[ni][1] = f2tf(y1 - __uint_as_float(bh[ni][1]));
                }
            }
#pragma unroll
            for (int mi = 0; mi < 2; mi++)
#pragma unroll
                for (int ni = 0; ni < 4; ni++) {
                    if (SPLIT == 3) {
                        mma_m16n8k8(acc[mi][ni], al[mi], bh[ni]);
                        mma_m16n8k8(acc[mi][ni], ah[mi], bl[ni]);
                    }
                    mma_m16n8k8(acc[mi][ni], ah[mi], bh[ni]);
                }
        }
        __syncthreads();
    }

#pragma unroll
    for (int mi = 0; mi < 2; mi++)
#pragma unroll
        for (int ni = 0; ni < 4; ni++) {
            const int r = m0 + wm * 32 + mi * 16 + gid;
            const int c = n0 + wn * 32 + ni * 8 + tig * 2;
            *reinterpret_cast<float2*>(C + (size_t)r * 512 + c) =
                make_float2(acc[mi][ni][0], acc[mi][ni][1]);
            *reinterpret_cast<float2*>(C + (size_t)(r + 8) * 512 + c) =
                make_float2(acc[mi][ni][2], acc[mi][ni][3]);
        }
}

// ---------------------------------------------------------------------------
// Per-(b,t,h) squared norms of qh / kh head slices
// ---------------------------------------------------------------------------
__global__ void norms_kernel()
{
    int idx = blockIdx.x * 256 + threadIdx.x;   // (row, h), 65536 total
    if (idx >= BT * Hq) return;
    int row = idx >> 3, h = idx & 7;
    const float* q = g_qh + (size_t)row * 512 + h * 64;
    const float* k = g_kh + (size_t)row * 512 + h * 64;
    float sq = 0.f, sk = 0.f;
#pragma unroll
    for (int i = 0; i < 16; i++) {
        float4 a = *reinterpret_cast<const float4*>(q + i * 4);
        sq += a.x * a.x + a.y * a.y + a.z * a.z + a.w * a.w;
        float4 c = *reinterpret_cast<const float4*>(k + i * 4);
        sk += c.x * c.x + c.y * c.y + c.z * c.z + c.w * c.w;
    }
    int b = row >> 10, t = row & 1023;
    g_q2[(size_t)(b * 8 + h) * 1024 + t] = sq;
    g_k2[(size_t)(b * 8 + h) * 1024 + t] = sk;
}

// ---------------------------------------------------------------------------
// Fused attention: per (b,h, 128-row q tile), loop over 64-key tiles:
//   S = exp(-(q2 + k2 - 2 Q K^T))  [3xTF32 for QK^T]
//   write S to attn_weights output, accumulate P += S @ V [TF32]
// ---------------------------------------------------------------------------
constexpr int ATTN_SMEM = (128 * 68 + 128 * 68 + 64 * 68 + 64 * 72 + 128 + 64) * 4; // 106240 B

__global__ void __launch_bounds__(256) attn_kernel(float* __restrict__ Sout)
{
    extern __shared__ float sm[];
    float* Qs  = sm;                    // [128][68]
    float* Ss  = Qs + 128 * 68;         // [128][68]
    float* Ks  = Ss + 128 * 68;         // [64][68]
    float* Vs  = Ks + 64 * 68;          // [64][72]
    float* q2s = Vs + 64 * 72;          // [128]
    float* k2s = q2s + 128;             // [64]

    const int tid = threadIdx.x;
    const int lane = tid & 31, warp = tid >> 5;
    const int gid = lane >> 2, tig = lane & 3;
    const int wm = warp & 3, wn = warp >> 2;
    const int bh = blockIdx.y, b = bh >> 3, h = bh & 7;
    const int m0 = blockIdx.x * 128;

    // Load Q tile [128 x 64]
    const float* qbase = g_qh + ((size_t)(b * 1024 + m0)) * 512 + h * 64;
#pragma unroll
    for (int i = 0; i < 8; i++) {
        int idx = tid + i * 256;            // 2048 float4
        int r = idx >> 4, c = (idx & 15) << 2;
        const float4 v = *reinterpret_cast<const float4*>(qbase + (size_t)r * 512 + c);
        Qs[r * 68 + c] = v.x; Qs[r * 68 + c + 1] = v.y;
        Qs[r * 68 + c + 2] = v.z; Qs[r * 68 + c + 3] = v.w;
    }
    if (tid < 128) q2s[tid] = g_q2[(size_t)bh * 1024 + m0 + tid];

    float pacc[2][4][4] = {};

    for (int nt = 0; nt < 16; nt++) {
        const int n0 = nt * 64;
        __syncthreads();    // protect Ks/Vs/k2s (and Qs/q2s on first iter)

        const float* kbase = g_kh + ((size_t)(b * 1024 + n0)) * 512 + h * 64;
        const float* vbase = g_vh + ((size_t)(b * 1024 + n0)) * 512 + h * 64;
#pragma unroll
        for (int i = 0; i < 4; i++) {
            int idx = tid + i * 256;        // 1024 float4 each
            int r = idx >> 4, c = (idx & 15) << 2;
            const float4 kv = *reinterpret_cast<const float4*>(kbase + (size_t)r * 512 + c);
            Ks[r * 68 + c] = kv.x; Ks[r * 68 + c + 1] = kv.y;
            Ks[r * 68 + c + 2] = kv.z; Ks[r * 68 + c + 3] = kv.w;
            const float4 vv = *reinterpret_cast<const float4*>(vbase + (size_t)r * 512 + c);
            Vs[r * 72 + c] = vv.x; Vs[r * 72 + c + 1] = vv.y;
            Vs[r * 72 + c + 2] = vv.z; Vs[r * 72 + c + 3] = vv.w;
        }
        if (tid < 64) k2s[tid] = g_k2[(size_t)bh * 1024 + n0 + tid];
        __syncthreads();

        // ---- QK^T (3xTF32 split) ----
        float sacc[2][4][4] = {};
#pragma unroll
        for (int s = 0; s < 8; s++) {
            const int kk = s * 8;
            unsigned ah[2][4], al[2][4];
#pragma unroll
            for (int mi = 0; mi < 2; mi++) {
                const int r0 = wm * 32 + mi * 16;
                float x0 = Qs[(r0 + gid) * 68 + kk + tig];
                float x1 = Qs[(r0 + gid + 8) * 68 + kk + tig];
                float x2 = Qs[(r0 + gid) * 68 + kk + tig + 4];
                float x3 = Qs[(r0 + gid + 8) * 68 + kk + tig + 4];
                ah[mi][0] = f2tf(x0); ah[mi][1] = f2tf(x1);
                ah[mi][2] = f2tf(x2); ah[mi][3] = f2tf(x3);
                al[mi][0] = f2tf(x0 - __uint_as_float(ah[mi][0]));
                al[mi][1] = f2tf(x1 - __uint_as_float(ah[mi][1]));
                al[mi][2] = f2tf(x2 - __uint_as_float(ah[mi][2]));
                al[mi][3] = f2tf(x3 - __uint_as_float(ah[mi][3]));
            }
            unsigned bh_[4][2], bl_[4][2];
#pragma unroll
            for (int ni = 0; ni < 4; ni++) {
                const int c0 = wn * 32 + ni * 8 + gid;          // key idx in tile
                float y0 = Ks[c0 * 68 + kk + tig];
                float y1 = Ks[c0 * 68 + kk + tig + 4];
                bh_[ni][0] = f2tf(y0); bh_[ni][1] = f2tf(y1);
                bl_[ni][0] = f2tf(y0 - __uint_as_float(bh_[ni][0]));
                bl_[ni][1] = f2tf(y1 - __uint_as_float(bh_[ni][1]));
            }
#pragma unroll
            for (int mi = 0; mi < 2; mi++)
#pragma unroll
                for (int ni = 0; ni < 4; ni++) {
                    mma_m16n8k8(sacc[mi][ni], al[mi], bh_[ni]);
                    mma_m16n8k8(sacc[mi][ni], ah[mi], bl_[ni]);
                    mma_m16n8k8(sacc[mi][ni], ah[mi], bh_[ni]);
                }
        }

        // ---- exp epilogue: write S to gmem + smem ----
#pragma unroll
        for (int mi = 0; mi < 2; mi++)
#pragma unroll
            for (int ni = 0; ni < 4; ni++) {
                const int r = wm * 32 + mi * 16 + gid;
                const int c = wn * 32 + ni * 8 + tig * 2;
                float q2a = q2s[r], q2b = q2s[r + 8];
                float k2a = k2s[c], k2b = k2s[c + 1];
                float e00 = __expf(-(q2a + k2a - 2.f * sacc[mi][ni][0]));
                float e01 = __expf(-(q2a + k2b - 2.f * sacc[mi][ni][1]));
                float e10 = __expf(-(q2b + k2a - 2.f * sacc[mi][ni][2]));
                float e11 = __expf(-(q2b + k2b - 2.f * sacc[mi][ni][3]));
                *reinterpret_cast<float2*>(&Ss[r * 68 + c]) = make_float2(e00, e01);
                *reinterpret_cast<float2*>(&Ss[(r + 8) * 68 + c]) = make_float2(e10, e11);
                if (Sout) {
                    *reinterpret_cast<float2*>(
                        Sout + ((size_t)bh * 1024 + m0 + r) * 1024 + n0 + c) = make_float2(e00, e01);
                    *reinterpret_cast<float2*>(
                        Sout + ((size_t)bh * 1024 + m0 + r + 8) * 1024 + n0 + c) = make_float2(e10, e11);
                }
            }
        __syncthreads();    // Ss fully written (cross-warp) before S@V

        // ---- P += S @ V (TF32) ----
#pragma unroll
        for (int s = 0; s < 8; s++) {
            const int kk = s * 8;
            unsigned af[2][4];
#pragma unroll
            for (int mi = 0; mi < 2; mi++) {
                const int r0 = wm * 32 + mi * 16;
                af[mi][0] = f2tf(Ss[(r0 + gid) * 68 + kk + tig]);
                af[mi][1] = f2tf(Ss[(r0 + gid + 8) * 68 + kk + tig]);
                af[mi][2] = f2tf(Ss[(r0 + gid) * 68 + kk + tig + 4]);
                af[mi][3] = f2tf(Ss[(r0 + gid + 8) * 68 + kk + tig + 4]);
            }
            unsigned bf[4][2];
#pragma unroll
            for (int ni = 0; ni < 4; ni++) {
                const int c0 = wn * 32 + ni * 8 + gid;          // kd col
                bf[ni][0] = f2tf(Vs[(kk + tig) * 72 + c0]);
                bf[ni][1] = f2tf(Vs[(kk + tig + 4) * 72 + c0]);
            }
#pragma unroll
            for (int mi = 0; mi < 2; mi++)
#pragma unroll
                for (int ni = 0; ni < 4; ni++)
                    mma_m16n8k8(pacc[mi][ni], af[mi], bf[ni]);
        }
    }

    // write P tile -> g_at [B*T, H*KD]
#pragma unroll
    for (int mi = 0; mi < 2; mi++)
#pragma unroll
        for (int ni = 0; ni < 4; ni++) {
            const int r = m0 + wm * 32 + mi * 16 + gid;
            const int c = h * 64 + wn * 32 + ni * 8 + tig * 2;
            float* dst = g_at + (size_t)(b * 1024 + r) * 512 + c;
            *reinterpret_cast<float2*>(dst) = make_float2(pacc[mi][ni][0], pacc[mi][ni][1]);
            *reinterpret_cast<float2*>(dst + (size_t)8 * 512) =
                make_float2(pacc[mi][ni][2], pacc[mi][ni][3]);
        }
}

// ---------------------------------------------------------------------------
extern "C" void kernel_launch(void* const* d_in, const int* in_sizes, int n_in,
                              void* d_out, int out_size)
{
    const float* query = (const float*)d_in[0];
    const float* key_  = (const float*)d_in[1];
    const float* value = (const float*)d_in[2];
    const float* Wq = (const float*)d_in[3];
    const float* Wk = (const float*)d_in[4];
    const float* Wv = (const float*)d_in[5];
    const float* Wo = (const float*)d_in[6];

    float *qh, *kh, *vh, *at;
    cudaGetSymbolAddress((void**)&qh, g_qh);
    cudaGetSymbolAddress((void**)&kh, g_kh);
    cudaGetSymbolAddress((void**)&vh, g_vh);
    cudaGetSymbolAddress((void**)&at, g_at);

    // Output layout: reference returns (out, attn_weights) -> expect both,
    // flattened in order. Handle single-output fallbacks defensively.
    float* outp = nullptr;
    float* attnW = nullptr;
    long long osz = (long long)out_size;
    if (osz >= NOUT + NATT) { outp = (float*)d_out; attnW = (float*)d_out + NOUT; }
    else if (osz >= NATT)   { attnW = (float*)d_out; }
    else                    { outp = (float*)d_out; }

    dim3 gg(8, 64);   // (N/64, M/128)
    gemm_k512<3><<<gg, 256>>>(query, Wq, qh);
    gemm_k512<3><<<gg, 256>>>(key_,  Wk, kh);
    gemm_k512<1><<<gg, 256>>>(value, Wv, vh);
    norms_kernel<<<(BT * Hq + 255) / 256, 256>>>();

    cudaFuncSetAttribute((const void*)attn_kernel,
                         cudaFuncAttributeMaxDynamicSharedMemorySize, ATTN_SMEM);
    attn_kernel<<<dim3(8, 64), 256, ATTN_SMEM>>>(attnW);

    if (outp) gemm_k512<1><<<gg, 256>>>(at, Wo, outp);
}

// round 9
// speedup vs baseline: 1.2110x; 1.2110x over previous
#include <cuda_runtime.h>
#include <cstdint>

// Problem constants
constexpr int Bq = 8, Tq = 1024, Dq = 512, Hq = 8, KDq = 64;
constexpr int BT = Bq * Tq;          // 8192
constexpr long long NOUT = (long long)BT * Dq;              // 4,194,304
constexpr long long NATT = (long long)Bq * Hq * Tq * Tq;    // 67,108,864

// Scratch (device globals: allocation-free rule)
__device__ float g_qh[BT * Dq];
__device__ float g_kh[BT * Dq];
__device__ float g_vh[BT * Dq];
__device__ float g_at[BT * Dq];
__device__ float g_q2[Bq * Hq * Tq];
__device__ float g_k2[Bq * Hq * Tq];

__device__ __forceinline__ unsigned f2tf(float x) {
    unsigned r;
    asm("cvt.rna.tf32.f32 %0, %1;" : "=r"(r) : "f"(x));
    return r;
}
__device__ __forceinline__ unsigned fbits(float x) { return __float_as_uint(x); }

__device__ __forceinline__ void mma_m16n8k8(float c[4], const unsigned a[4], const unsigned b[2]) {
    asm volatile(
        "mma.sync.aligned.m16n8k8.row.col.f32.tf32.tf32.f32 "
        "{%0,%1,%2,%3}, {%4,%5,%6,%7}, {%8,%9}, {%0,%1,%2,%3};"
        : "+f"(c[0]), "+f"(c[1]), "+f"(c[2]), "+f"(c[3])
        : "r"(a[0]), "r"(a[1]), "r"(a[2]), "r"(a[3]), "r"(b[0]), "r"(b[1]));
}

// ---------------------------------------------------------------------------
// K=512 GEMM: C[8192,512] = A[8192,512] @ W[512,512]
// Block tile 128x64, 256 threads (warp grid 4x2, warp tile 32x32).
// SPLIT=3: 3xTF32 via hi/lo staged in smem (cvt at STORE time, not read time).
// SPLIT=1: plain tf32 (raw fp32 in smem; HMMA truncates low mantissa bits).
// ---------------------------------------------------------------------------
template <int SPLIT>
__global__ void __launch_bounds__(256) gemm_k512(
    const float* __restrict__ A, const float* __restrict__ W, float* __restrict__ C)
{
    __shared__ float Ah[128][36];
    __shared__ float Al[(SPLIT == 3) ? 128 : 1][36];
    __shared__ float Wh[32][72];
    __shared__ float Wl[(SPLIT == 3) ? 32 : 1][72];

    const int tid = threadIdx.x;
    const int lane = tid & 31, warp = tid >> 5;
    const int gid = lane >> 2, tig = lane & 3;
    const int wm = warp & 3, wn = warp >> 2;
    const int m0 = blockIdx.y * 128, n0 = blockIdx.x * 64;

    float acc[2][4][4] = {};

    for (int k0 = 0; k0 < 512; k0 += 32) {
#pragma unroll
        for (int i = 0; i < 4; i++) {
            int idx = tid + i * 256;        // 1024 float4 for A 128x32
            int r = idx >> 3, c = (idx & 7) << 2;
            const float4 v = *reinterpret_cast<const float4*>(A + (size_t)(m0 + r) * 512 + k0 + c);
            if (SPLIT == 3) {
                float h0 = __uint_as_float(f2tf(v.x)), h1 = __uint_as_float(f2tf(v.y));
                float h2 = __uint_as_float(f2tf(v.z)), h3 = __uint_as_float(f2tf(v.w));
                Ah[r][c] = h0; Ah[r][c + 1] = h1; Ah[r][c + 2] = h2; Ah[r][c + 3] = h3;
                Al[r][c] = v.x - h0; Al[r][c + 1] = v.y - h1;
                Al[r][c + 2] = v.z - h2; Al[r][c + 3] = v.w - h3;
            } else {
                Ah[r][c] = v.x; Ah[r][c + 1] = v.y; Ah[r][c + 2] = v.z; Ah[r][c + 3] = v.w;
            }
        }
#pragma unroll
        for (int i = 0; i < 2; i++) {
            int idx = tid + i * 256;        // 512 float4 for W 32x64
            int r = idx >> 4, c = (idx & 15) << 2;
            const float4 v = *reinterpret_cast<const float4*>(W + (size_t)(k0 + r) * 512 + n0 + c);
            if (SPLIT == 3) {
                float h0 = __uint_as_float(f2tf(v.x)), h1 = __uint_as_float(f2tf(v.y));
                float h2 = __uint_as_float(f2tf(v.z)), h3 = __uint_as_float(f2tf(v.w));
                Wh[r][c] = h0; Wh[r][c + 1] = h1; Wh[r][c + 2] = h2; Wh[r][c + 3] = h3;
                Wl[r][c] = v.x - h0; Wl[r][c + 1] = v.y - h1;
                Wl[r][c + 2] = v.z - h2; Wl[r][c + 3] = v.w - h3;
            } else {
                Wh[r][c] = v.x; Wh[r][c + 1] = v.y; Wh[r][c + 2] = v.z; Wh[r][c + 3] = v.w;
            }
        }
        __syncthreads();

#pragma unroll
        for (int s = 0; s < 4; s++) {
            const int kk = s * 8;
            unsigned ah[2][4], al[2][4];
#pragma unroll
            for (int mi = 0; mi < 2; mi++) {
                const int r0 = wm * 32 + mi * 16;
                ah[mi][0] = fbits(Ah[r0 + gid][kk + tig]);
                ah[mi][1] = fbits(Ah[r0 + gid + 8][kk + tig]);
                ah[mi][2] = fbits(Ah[r0 + gid][kk + tig + 4]);
                ah[mi][3] = fbits(Ah[r0 + gid + 8][kk + tig + 4]);
                if (SPLIT == 3) {
                    al[mi][0] = fbits(Al[r0 + gid][kk + tig]);
                    al[mi][1] = fbits(Al[r0 + gid + 8][kk + tig]);
                    al[mi][2] = fbits(Al[r0 + gid][kk + tig + 4]);
                    al[mi][3] = fbits(Al[r0 + gid + 8][kk + tig + 4]);
                }
            }
            unsigned bh[4][2], bl[4][2];
#pragma unroll
            for (int ni = 0; ni < 4; ni++) {
                const int c0 = wn * 32 + ni * 8 + gid;
                bh[ni][0] = fbits(Wh[kk + tig][c0]);
                bh[ni][1] = fbits(Wh[kk + tig + 4][c0]);
                if (SPLIT == 3) {
                    bl[ni][0] = fbits(Wl[kk + tig][c0]);
                    bl[ni][1] = fbits(Wl[kk + tig + 4][c0]);
                }
            }
#pragma unroll
            for (int mi = 0; mi < 2; mi++)
#pragma unroll
                for (int ni = 0; ni < 4; ni++) {
                    if (SPLIT == 3) {
                        mma_m16n8k8(acc[mi][ni], al[mi], bh[ni]);
                        mma_m16n8k8(acc[mi][ni], ah[mi], bl[ni]);
                    }
                    mma_m16n8k8(acc[mi][ni], ah[mi], bh[ni]);
                }
        }
        __syncthreads();
    }

#pragma unroll
    for (int mi = 0; mi < 2; mi++)
#pragma unroll
        for (int ni = 0; ni < 4; ni++) {
            const int r = m0 + wm * 32 + mi * 16 + gid;
            const int c = n0 + wn * 32 + ni * 8 + tig * 2;
            *reinterpret_cast<float2*>(C + (size_t)r * 512 + c) =
                make_float2(acc[mi][ni][0], acc[mi][ni][1]);
            *reinterpret_cast<float2*>(C + (size_t)(r + 8) * 512 + c) =
                make_float2(acc[mi][ni][2], acc[mi][ni][3]);
        }
}

// ---------------------------------------------------------------------------
__global__ void norms_kernel()
{
    int idx = blockIdx.x * 256 + threadIdx.x;
    if (idx >= BT * Hq) return;
    int row = idx >> 3, h = idx & 7;
    const float* q = g_qh + (size_t)row * 512 + h * 64;
    const float* k = g_kh + (size_t)row * 512 + h * 64;
    float sq = 0.f, sk = 0.f;
#pragma unroll
    for (int i = 0; i < 16; i++) {
        float4 a = *reinterpret_cast<const float4*>(q + i * 4);
        sq += a.x * a.x + a.y * a.y + a.z * a.z + a.w * a.w;
        float4 c = *reinterpret_cast<const float4*>(k + i * 4);
        sk += c.x * c.x + c.y * c.y + c.z * c.z + c.w * c.w;
    }
    int b = row >> 10, t = row & 1023;
    g_q2[(size_t)(b * 8 + h) * 1024 + t] = sq;
    g_k2[(size_t)(b * 8 + h) * 1024 + t] = sk;
}

// ---------------------------------------------------------------------------
// Fused attention (mma.sync tf32), optimized:
//  - Q pre-split hi/lo into smem ONCE (no per-tile cvt)
//  - K split at store; V, S stored raw fp32 (HMMA truncates to tf32)
//  - mainloop is pure LDS + HMMA
//  - next K/V tile prefetched into registers to overlap gmem latency
// smem layout (floats), strides: 68 for 64-col K-major tiles, 72 for V
// ---------------------------------------------------------------------------
constexpr int OQH = 0;                    // Q hi   [128][68]
constexpr int OQL = OQH + 128 * 68;       // Q lo   [128][68]
constexpr int OKH = OQL + 128 * 68;       // K hi   [64][68]
constexpr int OKL = OKH + 64 * 68;        // K lo   [64][68]
constexpr int OVS = OKL + 64 * 68;        // V      [64][72]
constexpr int OSS = OVS + 64 * 72;        // S      [128][68]
constexpr int OQ2 = OSS + 128 * 68;       // q2     [128]
constexpr int OK2 = OQ2 + 128;            // k2     [64]
constexpr int ATTN_SMEM = (OK2 + 64) * 4; // 158464 bytes

__global__ void __launch_bounds__(256) attn_mma(float* __restrict__ Sout)
{
    extern __shared__ float sm[];
    const int tid = threadIdx.x, lane = tid & 31, warp = tid >> 5;
    const int gid = lane >> 2, tig = lane & 3;
    const int wm = warp & 3, wn = warp >> 2;
    const int bh = blockIdx.y, b = bh >> 3, h = bh & 7;
    const int m0 = blockIdx.x * 128;

    // --- Q tile load + hi/lo split (once) ---
    const float* qb = g_qh + ((size_t)(b * 1024 + m0)) * 512 + h * 64;
#pragma unroll
    for (int i = 0; i < 8; i++) {
        int idx = tid + i * 256;            // 2048 float4
        int r = idx >> 4, c = (idx & 15) << 2;
        float4 v = *reinterpret_cast<const float4*>(qb + (size_t)r * 512 + c);
        float h0 = __uint_as_float(f2tf(v.x)), h1 = __uint_as_float(f2tf(v.y));
        float h2 = __uint_as_float(f2tf(v.z)), h3 = __uint_as_float(f2tf(v.w));
        float* qh = sm + OQH + r * 68 + c;
        qh[0] = h0; qh[1] = h1; qh[2] = h2; qh[3] = h3;
        float* ql = sm + OQL + r * 68 + c;
        ql[0] = v.x - h0; ql[1] = v.y - h1; ql[2] = v.z - h2; ql[3] = v.w - h3;
    }
    if (tid < 128) sm[OQ2 + tid] = g_q2[(size_t)bh * 1024 + m0 + tid];

    const float* kb0 = g_kh + ((size_t)b * 1024) * 512 + h * 64;
    const float* vb0 = g_vh + ((size_t)b * 1024) * 512 + h * 64;

    // --- prefetch tile 0 into registers ---
    float4 kreg[4], vreg[4];
    float k2v = 0.f;
#pragma unroll
    for (int i = 0; i < 4; i++) {
        int idx = tid + i * 256;            // 1024 float4 each
        int r = idx >> 4, c = (idx & 15) << 2;
        kreg[i] = *reinterpret_cast<const float4*>(kb0 + (size_t)r * 512 + c);
        vreg[i] = *reinterpret_cast<const float4*>(vb0 + (size_t)r * 512 + c);
    }
    if (tid < 64) k2v = g_k2[(size_t)bh * 1024 + tid];

    float pacc[2][4][4] = {};

    for (int nt = 0; nt < 16; nt++) {
        __syncthreads();   // prev iter's QK/SV reads of Kh/Kl/Vs done

        // ---- store prefetched K (split) / V (raw) / k2 ----
#pragma unroll
        for (int i = 0; i < 4; i++) {
            int idx = tid + i * 256;
            int r = idx >> 4, c = (idx & 15) << 2;
            float4 v = kreg[i];
            float h0 = __uint_as_float(f2tf(v.x)), h1 = __uint_as_float(f2tf(v.y));
            float h2 = __uint_as_float(f2tf(v.z)), h3 = __uint_as_float(f2tf(v.w));
            float* kh = sm + OKH + r * 68 + c;
            kh[0] = h0; kh[1] = h1; kh[2] = h2; kh[3] = h3;
            float* kl = sm + OKL + r * 68 + c;
            kl[0] = v.x - h0; kl[1] = v.y - h1; kl[2] = v.z - h2; kl[3] = v.w - h3;
            float4 w = vreg[i];
            *reinterpret_cast<float4*>(sm + OVS + r * 72 + c) = w;
        }
        if (tid < 64) sm[OK2 + tid] = k2v;
        __syncthreads();

        // ---- prefetch next tile (overlaps with QK/exp/SV below) ----
        if (nt < 15) {
            const int n1 = (nt + 1) * 64;
#pragma unroll
            for (int i = 0; i < 4; i++) {
                int idx = tid + i * 256;
                int r = idx >> 4, c = (idx & 15) << 2;
                kreg[i] = *reinterpret_cast<const float4*>(
                    kb0 + (size_t)(n1 + r) * 512 + c);
                vreg[i] = *reinterpret_cast<const float4*>(
                    vb0 + (size_t)(n1 + r) * 512 + c);
            }
            if (tid < 64) k2v = g_k2[(size_t)bh * 1024 + n1 + tid];
        }

        // ---- QK^T: 3xTF32, pure LDS + HMMA ----
        float sacc[2][4][4] = {};
#pragma unroll
        for (int s = 0; s < 8; s++) {
            const int kk = s * 8;
            unsigned ah[2][4], al[2][4];
#pragma unroll
            for (int mi = 0; mi < 2; mi++) {
                const int r0 = wm * 32 + mi * 16;
                ah[mi][0] = fbits(sm[OQH + (r0 + gid) * 68 + kk + tig]);
                ah[mi][1] = fbits(sm[OQH + (r0 + gid + 8) * 68 + kk + tig]);
                ah[mi][2] = fbits(sm[OQH + (r0 + gid) * 68 + kk + tig + 4]);
                ah[mi][3] = fbits(sm[OQH + (r0 + gid + 8) * 68 + kk + tig + 4]);
                al[mi][0] = fbits(sm[OQL + (r0 + gid) * 68 + kk + tig]);
                al[mi][1] = fbits(sm[OQL + (r0 + gid + 8) * 68 + kk + tig]);
                al[mi][2] = fbits(sm[OQL + (r0 + gid) * 68 + kk + tig + 4]);
                al[mi][3] = fbits(sm[OQL + (r0 + gid + 8) * 68 + kk + tig + 4]);
            }
            unsigned bhf[4][2], blf[4][2];
#pragma unroll
            for (int ni = 0; ni < 4; ni++) {
                const int c0 = wn * 32 + ni * 8 + gid;
                bhf[ni][0] = fbits(sm[OKH + c0 * 68 + kk + tig]);
                bhf[ni][1] = fbits(sm[OKH + c0 * 68 + kk + tig + 4]);
                blf[ni][0] = fbits(sm[OKL + c0 * 68 + kk + tig]);
                blf[ni][1] = fbits(sm[OKL + c0 * 68 + kk + tig + 4]);
            }
#pragma unroll
            for (int mi = 0; mi < 2; mi++)
#pragma unroll
                for (int ni = 0; ni < 4; ni++) {
                    mma_m16n8k8(sacc[mi][ni], al[mi], bhf[ni]);
                    mma_m16n8k8(sacc[mi][ni], ah[mi], blf[ni]);
                    mma_m16n8k8(sacc[mi][ni], ah[mi], bhf[ni]);
                }
        }

        // ---- exp epilogue: S -> smem (raw) + gmem ----
        const int n0 = nt * 64;
#pragma unroll
        for (int mi = 0; mi < 2; mi++)
#pragma unroll
            for (int ni = 0; ni < 4; ni++) {
                const int r = wm * 32 + mi * 16 + gid;
                const int c = wn * 32 + ni * 8 + tig * 2;
                float q2a = sm[OQ2 + r], q2b = sm[OQ2 + r + 8];
                float k2a = sm[OK2 + c], k2b = sm[OK2 + c + 1];
                float e00 = __expf(fmaf(2.f, sacc[mi][ni][0], -(q2a + k2a)));
                float e01 = __expf(fmaf(2.f, sacc[mi][ni][1], -(q2a + k2b)));
                float e10 = __expf(fmaf(2.f, sacc[mi][ni][2], -(q2b + k2a)));
                float e11 = __expf(fmaf(2.f, sacc[mi][ni][3], -(q2b + k2b)));
                *reinterpret_cast<float2*>(sm + OSS + r * 68 + c) = make_float2(e00, e01);
                *reinterpret_cast<float2*>(sm + OSS + (r + 8) * 68 + c) = make_float2(e10, e11);
                if (Sout) {
                    *reinterpret_cast<float2*>(
                        Sout + ((size_t)bh * 1024 + m0 + r) * 1024 + n0 + c) = make_float2(e00, e01);
                    *reinterpret_cast<float2*>(
                        Sout + ((size_t)bh * 1024 + m0 + r + 8) * 1024 + n0 + c) = make_float2(e10, e11);
                }
            }
        __syncthreads();   // Ss fully written (cross-warp) before S@V

        // ---- P += S @ V (tf32, raw operands truncated by HMMA) ----
#pragma unroll
        for (int s = 0; s < 8; s++) {
            const int kk = s * 8;
            unsigned af[2][4];
#pragma unroll
            for (int mi = 0; mi < 2; mi++) {
                const int r0 = wm * 32 + mi * 16;
                af[mi][0] = fbits(sm[OSS + (r0 + gid) * 68 + kk + tig]);
                af[mi][1] = fbits(sm[OSS + (r0 + gid + 8) * 68 + kk + tig]);
                af[mi][2] = fbits(sm[OSS + (r0 + gid) * 68 + kk + tig + 4]);
                af[mi][3] = fbits(sm[OSS + (r0 + gid + 8) * 68 + kk + tig + 4]);
            }
            unsigned bf[4][2];
#pragma unroll
            for (int ni = 0; ni < 4; ni++) {
                const int c0 = wn * 32 + ni * 8 + gid;
                bf[ni][0] = fbits(sm[OVS + (kk + tig) * 72 + c0]);
                bf[ni][1] = fbits(sm[OVS + (kk + tig + 4) * 72 + c0]);
            }
#pragma unroll
            for (int mi = 0; mi < 2; mi++)
#pragma unroll
                for (int ni = 0; ni < 4; ni++)
                    mma_m16n8k8(pacc[mi][ni], af[mi], bf[ni]);
        }
    }

    // ---- write P tile -> g_at [B*T, H*KD] ----
#pragma unroll
    for (int mi = 0; mi < 2; mi++)
#pragma unroll
        for (int ni = 0; ni < 4; ni++) {
            const int r = m0 + wm * 32 + mi * 16 + gid;
            const int c = h * 64 + wn * 32 + ni * 8 + tig * 2;
            float* dst = g_at + (size_t)(b * 1024 + r) * 512 + c;
            *reinterpret_cast<float2*>(dst) = make_float2(pacc[mi][ni][0], pacc[mi][ni][1]);
            *reinterpret_cast<float2*>(dst + (size_t)8 * 512) =
                make_float2(pacc[mi][ni][2], pacc[mi][ni][3]);
        }
}

// ---------------------------------------------------------------------------
extern "C" void kernel_launch(void* const* d_in, const int* in_sizes, int n_in,
                              void* d_out, int out_size)
{
    const float* query = (const float*)d_in[0];
    const float* key_  = (const float*)d_in[1];
    const float* value = (const float*)d_in[2];
    const float* Wq = (const float*)d_in[3];
    const float* Wk = (const float*)d_in[4];
    const float* Wv = (const float*)d_in[5];
    const float* Wo = (const float*)d_in[6];

    float *qh, *kh, *vh, *at;
    cudaGetSymbolAddress((void**)&qh, g_qh);
    cudaGetSymbolAddress((void**)&kh, g_kh);
    cudaGetSymbolAddress((void**)&vh, g_vh);
    cudaGetSymbolAddress((void**)&at, g_at);

    // Output layout: reference returns (out, attn_weights), flattened in order.
    float* outp = nullptr;
    float* attnW = nullptr;
    long long osz = (long long)out_size;
    if (osz >= NOUT + NATT) { outp = (float*)d_out; attnW = (float*)d_out + NOUT; }
    else if (osz >= NATT)   { attnW = (float*)d_out; }
    else                    { outp = (float*)d_out; }

    dim3 gg(8, 64);   // (N/64, M/128)
    gemm_k512<3><<<gg, 256>>>(query, Wq, qh);
    gemm_k512<3><<<gg, 256>>>(key_,  Wk, kh);
    gemm_k512<1><<<gg, 256>>>(value, Wv, vh);
    norms_kernel<<<(BT * Hq + 255) / 256, 256>>>();

    cudaFuncSetAttribute((const void*)attn_mma,
                         cudaFuncAttributeMaxDynamicSharedMemorySize, ATTN_SMEM);
    attn_mma<<<dim3(8, 64), 256, ATTN_SMEM>>>(attnW);

    if (outp) gemm_k512<1><<<gg, 256>>>(at, Wo, outp);
}